// round 11
// baseline (speedup 1.0000x reference)
#include <cuda_runtime.h>

#define NN 100000
#define EE 1600000
#define FT 128

// Scratch (allocation-free rule: __device__ globals; 16B-aligned for v4 ops)
__device__ __align__(16) float g_xs[(size_t)NN * FT];   // (seq @ W^T) * dinv[row]
__device__ __align__(16) float g_W3[FT * 256];          // W dup layout: [k][c][tc*2]
__device__ __align__(16) float g_deg[NN];
__device__ __align__(16) float g_dinv[NN];
__device__ __align__(16) float g_eval[EE];              // w[e]*dinv[row] (CSR order)
__device__ int   g_ecol[EE];                            // col (CSR order)
__device__ int   g_rowptr[NN + 1];
__device__ int   g_cnt[NN];                             // histogram, then cursor

// ---------------------------------------------------------------------------
// 1) W -> duplicated k-major layout: g_W3[k*256 + (o&3)*64 + (o>>2)*2 + {0,1}]
// ---------------------------------------------------------------------------
__global__ void transpose_w_kernel(const float* __restrict__ W) {
    int idx = blockIdx.x * blockDim.x + threadIdx.x;
    if (idx < FT * FT) {
        int o = idx / FT, k = idx % FT;      // coalesced read of W[o][k]
        float w = W[idx];
        int c = o & 3, tcc = o >> 2;
        g_W3[k * 256 + c * 64 + tcc * 2 + 0] = w;
        g_W3[k * 256 + c * 64 + tcc * 2 + 1] = w;
    }
}

// ---------------------------------------------------------------------------
// 2) deg init to self-loop fill (3.0), counters to 0
// ---------------------------------------------------------------------------
__global__ void init_kernel() {
    int i = blockIdx.x * blockDim.x + threadIdx.x;
    if (i < NN) { g_deg[i] = 3.0f; g_cnt[i] = 0; }
}

// ---------------------------------------------------------------------------
// 3) Degree accumulation + row histogram (edge_index is int32)
// ---------------------------------------------------------------------------
__global__ void deg_hist_kernel(const int* __restrict__ ei,
                                const float* __restrict__ w) {
    int e = blockIdx.x * blockDim.x + threadIdx.x;
    if (e < EE) {
        int r = ei[e];
        atomicAdd(&g_deg[r], w[e]);
        atomicAdd(&g_cnt[r], 1);
    }
}

// ---------------------------------------------------------------------------
// 4) dinv = rsqrt(deg)  (deg >= 3 always)
// ---------------------------------------------------------------------------
__global__ void dinv_kernel() {
    int i = blockIdx.x * blockDim.x + threadIdx.x;
    if (i < NN) g_dinv[i] = rsqrtf(g_deg[i]);
}

// ---------------------------------------------------------------------------
// 5) Exclusive scan of g_cnt -> g_rowptr (single block), reset g_cnt to 0
// ---------------------------------------------------------------------------
#define SCAN_CHUNK 98   // 1024*98 >= NN
__global__ void __launch_bounds__(1024) scan_kernel() {
    __shared__ int sums[1024];
    int t = threadIdx.x;
    int lo = t * SCAN_CHUNK;
    int hi = lo + SCAN_CHUNK; if (hi > NN) hi = NN; if (lo > NN) lo = NN;
    int s = 0;
    for (int i = lo; i < hi; i++) s += g_cnt[i];
    sums[t] = s;
    __syncthreads();
    for (int off = 1; off < 1024; off <<= 1) {
        int v = (t >= off) ? sums[t - off] : 0;
        __syncthreads();
        sums[t] += v;
        __syncthreads();
    }
    int run = (t > 0) ? sums[t - 1] : 0;   // exclusive prefix of this chunk
    for (int i = lo; i < hi; i++) {
        g_rowptr[i] = run;
        run += g_cnt[i];
        g_cnt[i] = 0;                       // reset cursor for scatter
    }
    if (t == 1023) g_rowptr[NN] = run;
}

// ---------------------------------------------------------------------------
// 6) Scatter edges into CSR; fold w[e]*dinv[row] into stored value
// ---------------------------------------------------------------------------
__global__ void scatter_kernel(const int* __restrict__ ei,
                               const float* __restrict__ w) {
    int e = blockIdx.x * blockDim.x + threadIdx.x;
    if (e >= EE) return;
    int r = ei[e];
    int c = ei[EE + e];
    int pos = g_rowptr[r] + atomicAdd(&g_cnt[r], 1);
    g_ecol[pos] = c;
    g_eval[pos] = w[e] * g_dinv[r];
}

// ---------------------------------------------------------------------------
// 7) GEMM (f32x2 packed): g_xs[n] = (seq[n] @ W^T) * dinv[n]
//    64 rows x 128 cols per block, 256 threads.
//    acc2[jp][c] = {row 2jp, row 2jp+1} at column tc*4+c.
//    A tile k-major (stride 66), W tile pre-duplicated: both LDS.64, no packs.
// ---------------------------------------------------------------------------
__global__ void __launch_bounds__(256) gemm_kernel(const float* __restrict__ seq) {
    __shared__ __align__(16) float Ast[32 * 66];    // [k][row], padded stride
    __shared__ __align__(16) float Ws3[32 * 256];   // [k][c][tc*2] duplicated

    const int tid  = threadIdx.x;
    const int base = blockIdx.x * 64;
    int rows = NN - base; if (rows > 64) rows = 64;

    const int tc = tid & 31;    // 32 col-groups of 4
    const int tr = tid >> 5;    // 8 row-groups of 8 (whole warp shares tr)

    unsigned long long acc2[4][4];   // zero bits == {0.0f, 0.0f}
    #pragma unroll
    for (int jp = 0; jp < 4; jp++)
        #pragma unroll
        for (int c = 0; c < 4; c++) acc2[jp][c] = 0ULL;

    for (int k0 = 0; k0 < FT; k0 += 32) {
        __syncthreads();
        // A chunk transposed: thread reads float4 (row r, k c4*4..+3)
        #pragma unroll
        for (int i = 0; i < 2; i++) {
            int f = tid + 256 * i;
            int r = f >> 3, c4 = f & 7;
            float4 v = make_float4(0.f, 0.f, 0.f, 0.f);
            if (r < rows)
                v = *(const float4*)(seq + (size_t)(base + r) * FT + k0 + c4 * 4);
            Ast[(c4 * 4 + 0) * 66 + r] = v.x;
            Ast[(c4 * 4 + 1) * 66 + r] = v.y;
            Ast[(c4 * 4 + 2) * 66 + r] = v.z;
            Ast[(c4 * 4 + 3) * 66 + r] = v.w;
        }
        // W chunk: straight float4 copy of pre-duplicated layout (8KB*4)
        #pragma unroll
        for (int i = 0; i < 8; i++) {
            int f = tid + 256 * i;
            ((float4*)Ws3)[f] = *(const float4*)(g_W3 + (size_t)k0 * 256 + f * 4);
        }
        __syncthreads();

        #pragma unroll 8
        for (int k = 0; k < 32; k++) {
            unsigned long long ap[4], wd[4];
            #pragma unroll
            for (int jp = 0; jp < 4; jp++)   // broadcast LDS.64
                ap[jp] = *(const unsigned long long*)(Ast + k * 66 + tr * 8 + jp * 2);
            #pragma unroll
            for (int c = 0; c < 4; c++)      // 8B-stride conflict-free LDS.64
                wd[c] = *(const unsigned long long*)(Ws3 + k * 256 + c * 64 + tc * 2);
            #pragma unroll
            for (int jp = 0; jp < 4; jp++)
                #pragma unroll
                for (int c = 0; c < 4; c++)
                    asm("fma.rn.f32x2 %0, %1, %2, %0;"
                        : "+l"(acc2[jp][c]) : "l"(ap[jp]), "l"(wd[c]));
        }
    }

    // Epilogue: unpack pairs, scale by dinv[row], store g_xs
    #pragma unroll
    for (int jp = 0; jp < 4; jp++) {
        float v0[4], v1[4];
        #pragma unroll
        for (int c = 0; c < 4; c++)
            asm("mov.b64 {%0, %1}, %2;" : "=f"(v0[c]), "=f"(v1[c]) : "l"(acc2[jp][c]));
        int r0 = base + tr * 8 + jp * 2;
        int r1 = r0 + 1;
        if (r0 < NN) {
            float di = g_dinv[r0];
            *(float4*)(g_xs + (size_t)r0 * FT + tc * 4) =
                make_float4(v0[0] * di, v0[1] * di, v0[2] * di, v0[3] * di);
        }
        if (r1 < NN) {
            float di = g_dinv[r1];
            *(float4*)(g_xs + (size_t)r1 * FT + tc * 4) =
                make_float4(v1[0] * di, v1[1] * di, v1[2] * di, v1[3] * di);
        }
    }
}

// ---------------------------------------------------------------------------
// 8) Aggregation: warp per row, register accumulation, no atomics.
//    out[n] = relu( 3*dinv[n]*xs[n] + sum_e val[e] * xs[col[e]] )
//    Written directly to d_out (plain vector stores).
// ---------------------------------------------------------------------------
__global__ void __launch_bounds__(256) agg_kernel(float* __restrict__ out) {
    int n    = (blockIdx.x * blockDim.x + threadIdx.x) >> 5;
    int lane = threadIdx.x & 31;
    if (n >= NN) return;

    const float4* xs4 = (const float4*)g_xs;
    int start = g_rowptr[n];
    int end   = g_rowptr[n + 1];

    // self-loop: 3*dinv[n] * xs[n]
    float  s3 = 3.0f * g_dinv[n];
    float4 a  = xs4[(size_t)n * 32 + lane];
    float4 acc = make_float4(a.x * s3, a.y * s3, a.z * s3, a.w * s3);

    int idx = start;
    for (; idx + 2 <= end; idx += 2) {     // 2-way for MLP
        int   c0 = g_ecol[idx],     c1 = g_ecol[idx + 1];
        float s0 = g_eval[idx],     s1 = g_eval[idx + 1];
        float4 v0 = xs4[(size_t)c0 * 32 + lane];
        float4 v1 = xs4[(size_t)c1 * 32 + lane];
        acc.x += s0 * v0.x + s1 * v1.x;
        acc.y += s0 * v0.y + s1 * v1.y;
        acc.z += s0 * v0.z + s1 * v1.z;
        acc.w += s0 * v0.w + s1 * v1.w;
    }
    if (idx < end) {
        int   c = g_ecol[idx];
        float s = g_eval[idx];
        float4 v = xs4[(size_t)c * 32 + lane];
        acc.x += s * v.x; acc.y += s * v.y; acc.z += s * v.z; acc.w += s * v.w;
    }

    acc.x = fmaxf(acc.x, 0.0f); acc.y = fmaxf(acc.y, 0.0f);
    acc.z = fmaxf(acc.z, 0.0f); acc.w = fmaxf(acc.w, 0.0f);
    ((float4*)out)[(size_t)n * 32 + lane] = acc;
}

// ---------------------------------------------------------------------------
extern "C" void kernel_launch(void* const* d_in, const int* in_sizes, int n_in,
                              void* d_out, int out_size) {
    // Resolve inputs by element count (robust to metadata ordering)
    const float* seq = nullptr;
    const float* ew  = nullptr;
    const float* W   = nullptr;
    const int*   ei  = nullptr;
    for (int i = 0; i < n_in; i++) {
        if      (in_sizes[i] == NN * FT) seq = (const float*)d_in[i];
        else if (in_sizes[i] == EE)      ew  = (const float*)d_in[i];
        else if (in_sizes[i] == FT * FT) W   = (const float*)d_in[i];
        else if (in_sizes[i] == 2 * EE)  ei  = (const int*)d_in[i];
    }
    float* out = (float*)d_out;

    transpose_w_kernel<<<(FT * FT + 255) / 256, 256>>>(W);
    init_kernel<<<(NN + 255) / 256, 256>>>();
    deg_hist_kernel<<<(EE + 255) / 256, 256>>>(ei, ew);
    dinv_kernel<<<(NN + 255) / 256, 256>>>();
    scan_kernel<<<1, 1024>>>();
    scatter_kernel<<<(EE + 255) / 256, 256>>>(ei, ew);
    gemm_kernel<<<(NN + 63) / 64, 256>>>(seq);
    agg_kernel<<<(NN * 32 + 255) / 256, 256>>>(out);   // warp per row
}

// round 12
// speedup vs baseline: 1.0949x; 1.0949x over previous
#include <cuda_runtime.h>

#define NN 100000
#define EE 1600000
#define FT 128

// Scratch (allocation-free rule: __device__ globals; all 16B-aligned for v4 ops)
__device__ __align__(16) float g_xs[(size_t)NN * FT];   // (seq @ W^T) * dinv[row]
__device__ __align__(16) float g_out[(size_t)NN * FT];  // pre-ReLU accumulator
__device__ __align__(16) float g_deg[NN];
__device__ __align__(16) float g_dinv[NN];
__device__ __align__(16) float g_W3[FT * 256];          // W dup layout: [k][c][tc*2]

// ---------------------------------------------------------------------------
// 1) W -> duplicated k-major layout: g_W3[k*256 + (o&3)*64 + (o>>2)*2 + {0,1}]
//    (each output column o stored twice so GEMM loads pairs with LDS.64)
// ---------------------------------------------------------------------------
__global__ void transpose_w_kernel(const float* __restrict__ W) {
    int idx = blockIdx.x * blockDim.x + threadIdx.x;
    if (idx < FT * FT) {
        int o = idx / FT, k = idx % FT;      // coalesced read of W[o][k]
        float w = W[idx];
        int c = o & 3, tcc = o >> 2;
        g_W3[k * 256 + c * 64 + tcc * 2 + 0] = w;
        g_W3[k * 256 + c * 64 + tcc * 2 + 1] = w;
    }
}

// ---------------------------------------------------------------------------
// 2) deg init to self-loop fill (3.0)
// ---------------------------------------------------------------------------
__global__ void init_deg_kernel() {
    int i = blockIdx.x * blockDim.x + threadIdx.x;
    if (i < NN) g_deg[i] = 3.0f;
}

// ---------------------------------------------------------------------------
// 3) Degree accumulation: deg[row[e]] += w[e]   (edge_index is int32)
// ---------------------------------------------------------------------------
__global__ void deg_kernel(const int* __restrict__ ei,
                           const float* __restrict__ w) {
    int e = blockIdx.x * blockDim.x + threadIdx.x;
    if (e < EE) atomicAdd(&g_deg[ei[e]], w[e]);
}

// ---------------------------------------------------------------------------
// 4) dinv = rsqrt(deg)  (deg >= 3 always, guard vacuous)
// ---------------------------------------------------------------------------
__global__ void dinv_kernel() {
    int i = blockIdx.x * blockDim.x + threadIdx.x;
    if (i < NN) g_dinv[i] = rsqrtf(g_deg[i]);
}

// ---------------------------------------------------------------------------
// 5) GEMM (f32x2 packed) with fused scaling epilogue:
//      g_xs[n]  = (seq[n] @ W^T) * dinv[n]
//      g_out[n] = 3*dinv[n] * g_xs[n]      (self-loop init of accumulator)
//    64 rows x 128 cols per block, 256 threads.
//    acc2[jp][c] = packed {row 2jp, row 2jp+1} at column tc*4+c.
//    A tile k-major (stride 66) -> broadcast LDS.64 row-pairs;
//    W tile pre-duplicated -> 8B-stride conflict-free LDS.64. No pack MOVs.
// ---------------------------------------------------------------------------
__global__ void __launch_bounds__(256) gemm_kernel(const float* __restrict__ seq) {
    __shared__ __align__(16) float Ast[32 * 66];    // [k][row], padded stride
    __shared__ __align__(16) float Ws3[32 * 256];   // [k][c][tc*2] duplicated

    const int tid  = threadIdx.x;
    const int base = blockIdx.x * 64;
    int rows = NN - base; if (rows > 64) rows = 64;

    const int tc = tid & 31;    // 32 col-groups of 4
    const int tr = tid >> 5;    // 8 row-groups of 8 (whole warp shares tr)

    unsigned long long acc2[4][4];   // zero bits == {0.0f, 0.0f}
    #pragma unroll
    for (int jp = 0; jp < 4; jp++)
        #pragma unroll
        for (int c = 0; c < 4; c++) acc2[jp][c] = 0ULL;

    for (int k0 = 0; k0 < FT; k0 += 32) {
        __syncthreads();
        // A chunk transposed: thread reads float4 (row r, k = c4*4..+3)
        #pragma unroll
        for (int i = 0; i < 2; i++) {
            int f = tid + 256 * i;
            int r = f >> 3, c4 = f & 7;
            float4 v = make_float4(0.f, 0.f, 0.f, 0.f);
            if (r < rows)
                v = *(const float4*)(seq + (size_t)(base + r) * FT + k0 + c4 * 4);
            Ast[(c4 * 4 + 0) * 66 + r] = v.x;
            Ast[(c4 * 4 + 1) * 66 + r] = v.y;
            Ast[(c4 * 4 + 2) * 66 + r] = v.z;
            Ast[(c4 * 4 + 3) * 66 + r] = v.w;
        }
        // W chunk: straight float4 copy of pre-duplicated layout (32KB)
        #pragma unroll
        for (int i = 0; i < 8; i++) {
            int f = tid + 256 * i;
            ((float4*)Ws3)[f] = *(const float4*)(g_W3 + (size_t)k0 * 256 + f * 4);
        }
        __syncthreads();

        #pragma unroll 8
        for (int k = 0; k < 32; k++) {
            unsigned long long ap[4], wd[4];
            #pragma unroll
            for (int jp = 0; jp < 4; jp++)   // broadcast LDS.64 (warp shares tr)
                ap[jp] = *(const unsigned long long*)(Ast + k * 66 + tr * 8 + jp * 2);
            #pragma unroll
            for (int c = 0; c < 4; c++)      // 8B stride across lanes
                wd[c] = *(const unsigned long long*)(Ws3 + k * 256 + c * 64 + tc * 2);
            #pragma unroll
            for (int jp = 0; jp < 4; jp++)
                #pragma unroll
                for (int c = 0; c < 4; c++)
                    asm("fma.rn.f32x2 %0, %1, %2, %0;"
                        : "+l"(acc2[jp][c]) : "l"(ap[jp]), "l"(wd[c]));
        }
    }

    // Epilogue: unpack pairs, scale by dinv[row], store g_xs and g_out
    #pragma unroll
    for (int jp = 0; jp < 4; jp++) {
        float v0[4], v1[4];
        #pragma unroll
        for (int c = 0; c < 4; c++)
            asm("mov.b64 {%0, %1}, %2;" : "=f"(v0[c]), "=f"(v1[c]) : "l"(acc2[jp][c]));
        int r0 = base + tr * 8 + jp * 2;
        int r1 = r0 + 1;
        if (r0 < NN) {
            float di = g_dinv[r0];
            float s3 = 3.0f * di;
            float4 xs = make_float4(v0[0] * di, v0[1] * di, v0[2] * di, v0[3] * di);
            *(float4*)(g_xs  + (size_t)r0 * FT + tc * 4) = xs;
            *(float4*)(g_out + (size_t)r0 * FT + tc * 4) =
                make_float4(xs.x * s3, xs.y * s3, xs.z * s3, xs.w * s3);
        }
        if (r1 < NN) {
            float di = g_dinv[r1];
            float s3 = 3.0f * di;
            float4 xs = make_float4(v1[0] * di, v1[1] * di, v1[2] * di, v1[3] * di);
            *(float4*)(g_xs  + (size_t)r1 * FT + tc * 4) = xs;
            *(float4*)(g_out + (size_t)r1 * FT + tc * 4) =
                make_float4(xs.x * s3, xs.y * s3, xs.z * s3, xs.w * s3);
        }
    }
}

// ---------------------------------------------------------------------------
// 6) Edge aggregation: g_out[row] += (w[e]*dinv[row]) * g_xs[col]
//    (dinv[col] folded into g_xs). One warp per edge,
//    one red.global.add.v4.f32 per lane (16B vector reduction).
// ---------------------------------------------------------------------------
__global__ void __launch_bounds__(256) agg_kernel(const int* __restrict__ ei,
                                                  const float* __restrict__ w) {
    int gw   = (blockIdx.x * blockDim.x + threadIdx.x) >> 5;   // edge id
    int lane = threadIdx.x & 31;
    if (gw >= EE) return;

    int r = ei[gw];        // row
    int c = ei[EE + gw];   // col
    float s = w[gw] * g_dinv[r];

    float4 v = *(const float4*)(g_xs + (size_t)c * FT + lane * 4);
    float* p = g_out + (size_t)r * FT + lane * 4;
    asm volatile("red.global.add.v4.f32 [%0], {%1, %2, %3, %4};"
                 :: "l"(p),
                    "f"(v.x * s), "f"(v.y * s), "f"(v.z * s), "f"(v.w * s)
                 : "memory");
}

// ---------------------------------------------------------------------------
// 7) ReLU + copy to d_out (plain vector stores only on harness memory)
// ---------------------------------------------------------------------------
__global__ void relu_copy_kernel(float* __restrict__ out) {
    int i = blockIdx.x * blockDim.x + threadIdx.x;   // float4 index
    if (i >= NN * (FT / 4)) return;
    float4 v = ((const float4*)g_out)[i];
    v.x = fmaxf(v.x, 0.0f); v.y = fmaxf(v.y, 0.0f);
    v.z = fmaxf(v.z, 0.0f); v.w = fmaxf(v.w, 0.0f);
    ((float4*)out)[i] = v;
}

// ---------------------------------------------------------------------------
extern "C" void kernel_launch(void* const* d_in, const int* in_sizes, int n_in,
                              void* d_out, int out_size) {
    // Resolve inputs by element count (robust to metadata ordering):
    //   seq: NN*FT (12.8M f32), edge_weight: EE (1.6M f32),
    //   W: FT*FT (16384 f32), edge_index: 2*EE (3.2M i32)
    const float* seq = nullptr;
    const float* ew  = nullptr;
    const float* W   = nullptr;
    const int*   ei  = nullptr;
    for (int i = 0; i < n_in; i++) {
        if      (in_sizes[i] == NN * FT) seq = (const float*)d_in[i];
        else if (in_sizes[i] == EE)      ew  = (const float*)d_in[i];
        else if (in_sizes[i] == FT * FT) W   = (const float*)d_in[i];
        else if (in_sizes[i] == 2 * EE)  ei  = (const int*)d_in[i];
    }
    float* out = (float*)d_out;

    transpose_w_kernel<<<(FT * FT + 255) / 256, 256>>>(W);
    init_deg_kernel<<<(NN + 255) / 256, 256>>>();
    deg_kernel<<<(EE + 255) / 256, 256>>>(ei, ew);
    dinv_kernel<<<(NN + 255) / 256, 256>>>();
    gemm_kernel<<<(NN + 63) / 64, 256>>>(seq);        // epilogue needs dinv
    agg_kernel<<<(EE * 32) / 256, 256>>>(ei, ew);     // 1 warp / edge, exact grid
    relu_copy_kernel<<<(NN * (FT / 4) + 255) / 256, 256>>>(out);
}

// round 13
// speedup vs baseline: 1.2569x; 1.1480x over previous
#include <cuda_runtime.h>
#include <cuda_fp16.h>

#define NN 100000
#define EE 1600000
#define FT 128

// Scratch (allocation-free rule: __device__ globals; all 16B-aligned)
__device__ __align__(16) __half g_xsh[(size_t)NN * FT]; // fp16 (seq@W^T)*dinv[row]
__device__ __align__(16) float g_out[(size_t)NN * FT];  // pre-ReLU accumulator (fp32)
__device__ __align__(16) float g_deg[NN];
__device__ __align__(16) float g_dinv[NN];
__device__ __align__(16) float g_Wt[FT * FT];           // W transposed: Wt[k][o]

// ---------------------------------------------------------------------------
// 1) Transpose W once (tiny: 16K elements)
// ---------------------------------------------------------------------------
__global__ void transpose_w_kernel(const float* __restrict__ W) {
    int idx = blockIdx.x * blockDim.x + threadIdx.x;
    if (idx < FT * FT) {
        int o = idx / FT, k = idx % FT;      // coalesced read of W[o][k]
        g_Wt[k * FT + o] = W[idx];
    }
}

// ---------------------------------------------------------------------------
// 2) deg init to self-loop fill (3.0)
// ---------------------------------------------------------------------------
__global__ void init_deg_kernel() {
    int i = blockIdx.x * blockDim.x + threadIdx.x;
    if (i < NN) g_deg[i] = 3.0f;
}

// ---------------------------------------------------------------------------
// 3) Degree accumulation: deg[row[e]] += w[e]   (edge_index is int32)
// ---------------------------------------------------------------------------
__global__ void deg_kernel(const int* __restrict__ ei,
                           const float* __restrict__ w) {
    int e = blockIdx.x * blockDim.x + threadIdx.x;
    if (e < EE) atomicAdd(&g_deg[ei[e]], w[e]);
}

// ---------------------------------------------------------------------------
// 4) dinv = rsqrt(deg)  (deg >= 3 always, guard vacuous)
// ---------------------------------------------------------------------------
__global__ void dinv_kernel() {
    int i = blockIdx.x * blockDim.x + threadIdx.x;
    if (i < NN) g_dinv[i] = rsqrtf(g_deg[i]);
}

// ---------------------------------------------------------------------------
// 5) GEMM (scalar FFMA, known-good) with fused scaling epilogue:
//      g_xsh[n] = fp16( (seq[n] @ W^T) * dinv[n] )
//      g_out[n] = 3*dinv[n] * (xs fp32)        (self-loop init, full precision)
//    Block: 64 rows x 128 cols, 256 threads, 8x4 register tile per thread.
// ---------------------------------------------------------------------------
__global__ void __launch_bounds__(256) gemm_kernel(const float* __restrict__ seq) {
    __shared__ __align__(16) float As[64 * 32];    // 8KB  (row-major chunk)
    __shared__ __align__(16) float Ws[32 * FT];    // 16KB (K-major chunk)

    const int tid  = threadIdx.x;
    const int base = blockIdx.x * 64;
    int rows = NN - base; if (rows > 64) rows = 64;

    const int tc = tid & 31;    // 32 col-groups of 4
    const int tr = tid >> 5;    // 8 row-groups of 8 (whole warp shares tr)

    float acc[8][4];
    #pragma unroll
    for (int j = 0; j < 8; j++)
        #pragma unroll
        for (int c = 0; c < 4; c++) acc[j][c] = 0.0f;

    for (int k0 = 0; k0 < FT; k0 += 32) {
        __syncthreads();   // previous chunk's compute done before overwrite
        // A chunk: 64 rows x 32 k = 512 float4, 2 per thread
        #pragma unroll
        for (int i = 0; i < 2; i++) {
            int f = tid + 256 * i;
            int r = f >> 3, c4 = f & 7;
            float4 v = make_float4(0.f, 0.f, 0.f, 0.f);
            if (r < rows)
                v = *(const float4*)(seq + (size_t)(base + r) * FT + k0 + c4 * 4);
            *(float4*)(As + r * 32 + c4 * 4) = v;
        }
        // W chunk: rows k0..k0+31 of g_Wt = 1024 float4, 4 per thread
        #pragma unroll
        for (int i = 0; i < 4; i++) {
            int f = tid + 256 * i;
            ((float4*)Ws)[f] = *(const float4*)(g_Wt + (size_t)k0 * FT + f * 4);
        }
        __syncthreads();

        #pragma unroll
        for (int k = 0; k < 32; k++) {
            float4 wv = *(const float4*)(Ws + k * FT + tc * 4);
            #pragma unroll
            for (int j = 0; j < 8; j++) {
                float a = As[(tr * 8 + j) * 32 + k];   // warp-broadcast LDS
                acc[j][0] += a * wv.x;
                acc[j][1] += a * wv.y;
                acc[j][2] += a * wv.z;
                acc[j][3] += a * wv.w;
            }
        }
    }

    #pragma unroll
    for (int j = 0; j < 8; j++) {
        int r = base + tr * 8 + j;
        if (r < NN) {
            float di = g_dinv[r];          // warp-broadcast LDG (L2-resident)
            float s3 = 3.0f * di;
            float x0 = acc[j][0] * di, x1 = acc[j][1] * di;
            float x2 = acc[j][2] * di, x3 = acc[j][3] * di;
            // fp16 store of xs (gathered operand)
            __half2 h01 = __floats2half2_rn(x0, x1);
            __half2 h23 = __floats2half2_rn(x2, x3);
            uint2 pk;
            pk.x = *(unsigned*)&h01;
            pk.y = *(unsigned*)&h23;
            *(uint2*)(g_xsh + (size_t)r * FT + tc * 4) = pk;
            // fp32 self-loop init from pre-rounding xs
            *(float4*)(g_out + (size_t)r * FT + tc * 4) =
                make_float4(x0 * s3, x1 * s3, x2 * s3, x3 * s3);
        }
    }
}

// ---------------------------------------------------------------------------
// 6) Edge aggregation: g_out[row] += (w[e]*dinv[row]) * xs_fp16[col]
//    One warp per edge; lane gathers 4 halves (8B), converts, scales,
//    one red.global.add.v4.f32 (fp32 accumulation).
// ---------------------------------------------------------------------------
__global__ void __launch_bounds__(256) agg_kernel(const int* __restrict__ ei,
                                                  const float* __restrict__ w) {
    int gw   = (blockIdx.x * blockDim.x + threadIdx.x) >> 5;   // edge id
    int lane = threadIdx.x & 31;
    if (gw >= EE) return;

    int r = ei[gw];        // row
    int c = ei[EE + gw];   // col
    float s = w[gw] * g_dinv[r];

    uint2 pk = *(const uint2*)(g_xsh + (size_t)c * FT + lane * 4);
    __half2 h01 = *(__half2*)&pk.x;
    __half2 h23 = *(__half2*)&pk.y;
    float2 f01 = __half22float2(h01);
    float2 f23 = __half22float2(h23);

    float* p = g_out + (size_t)r * FT + lane * 4;
    asm volatile("red.global.add.v4.f32 [%0], {%1, %2, %3, %4};"
                 :: "l"(p),
                    "f"(f01.x * s), "f"(f01.y * s),
                    "f"(f23.x * s), "f"(f23.y * s)
                 : "memory");
}

// ---------------------------------------------------------------------------
// 7) ReLU + copy to d_out (plain vector stores only on harness memory)
// ---------------------------------------------------------------------------
__global__ void relu_copy_kernel(float* __restrict__ out) {
    int i = blockIdx.x * blockDim.x + threadIdx.x;   // float4 index
    if (i >= NN * (FT / 4)) return;
    float4 v = ((const float4*)g_out)[i];
    v.x = fmaxf(v.x, 0.0f); v.y = fmaxf(v.y, 0.0f);
    v.z = fmaxf(v.z, 0.0f); v.w = fmaxf(v.w, 0.0f);
    ((float4*)out)[i] = v;
}

// ---------------------------------------------------------------------------
extern "C" void kernel_launch(void* const* d_in, const int* in_sizes, int n_in,
                              void* d_out, int out_size) {
    // Resolve inputs by element count (robust to metadata ordering):
    //   seq: NN*FT (12.8M f32), edge_weight: EE (1.6M f32),
    //   W: FT*FT (16384 f32), edge_index: 2*EE (3.2M i32)
    const float* seq = nullptr;
    const float* ew  = nullptr;
    const float* W   = nullptr;
    const int*   ei  = nullptr;
    for (int i = 0; i < n_in; i++) {
        if      (in_sizes[i] == NN * FT) seq = (const float*)d_in[i];
        else if (in_sizes[i] == EE)      ew  = (const float*)d_in[i];
        else if (in_sizes[i] == FT * FT) W   = (const float*)d_in[i];
        else if (in_sizes[i] == 2 * EE)  ei  = (const int*)d_in[i];
    }
    float* out = (float*)d_out;

    transpose_w_kernel<<<(FT * FT + 255) / 256, 256>>>(W);
    init_deg_kernel<<<(NN + 255) / 256, 256>>>();
    deg_kernel<<<(EE + 255) / 256, 256>>>(ei, ew);
    dinv_kernel<<<(NN + 255) / 256, 256>>>();
    gemm_kernel<<<(NN + 63) / 64, 256>>>(seq);        // epilogue needs dinv
    agg_kernel<<<(EE * 32) / 256, 256>>>(ei, ew);     // 1 warp / edge, exact grid
    relu_copy_kernel<<<(NN * (FT / 4) + 255) / 256, 256>>>(out);
}

// round 15
// speedup vs baseline: 1.3374x; 1.0641x over previous
#include <cuda_runtime.h>
#include <cuda_fp16.h>
#include <cstdint>

#define NN 100000
#define EE 1600000
#define FT 128

// ---------------------------------------------------------------------------
// Scratch (allocation-free rule: __device__ globals)
// ---------------------------------------------------------------------------
__device__ __align__(16) __half g_xsh[(size_t)NN * FT];   // fp16 (seq@W^T)*dinv[row]
__device__ __align__(16) float  g_out[(size_t)NN * FT];   // pre-ReLU accumulator (fp32)
__device__ __align__(16) float  g_deg[NN];
__device__ __align__(16) float  g_dinv[NN];
__device__ __align__(16) __half g_Wh[FT * FT];            // W in fp16, row-major [o][k]

__device__ __forceinline__ uint32_t smem_u32(const void* p) {
    uint32_t a;
    asm("{ .reg .u64 t; cvta.to.shared.u64 t, %1; cvt.u32.u64 %0, t; }"
        : "=r"(a) : "l"(p));
    return a;
}

// ---------------------------------------------------------------------------
// 1) W -> fp16 (one-time, tiny)
// ---------------------------------------------------------------------------
__global__ void wh_kernel(const float* __restrict__ W) {
    int idx = blockIdx.x * blockDim.x + threadIdx.x;
    if (idx < FT * FT) g_Wh[idx] = __float2half_rn(W[idx]);
}

// ---------------------------------------------------------------------------
// 2) deg init to self-loop fill (3.0)
// ---------------------------------------------------------------------------
__global__ void init_deg_kernel() {
    int i = blockIdx.x * blockDim.x + threadIdx.x;
    if (i < NN) g_deg[i] = 3.0f;
}

// ---------------------------------------------------------------------------
// 3) Degree accumulation: deg[row[e]] += w[e]   (edge_index is int32)
// ---------------------------------------------------------------------------
__global__ void deg_kernel(const int* __restrict__ ei,
                           const float* __restrict__ w) {
    int e = blockIdx.x * blockDim.x + threadIdx.x;
    if (e < EE) atomicAdd(&g_deg[ei[e]], w[e]);
}

// ---------------------------------------------------------------------------
// 4) dinv = rsqrt(deg)  (deg >= 3 always, guard vacuous)
// ---------------------------------------------------------------------------
__global__ void dinv_kernel() {
    int i = blockIdx.x * blockDim.x + threadIdx.x;
    if (i < NN) g_dinv[i] = rsqrtf(g_deg[i]);
}

// ---------------------------------------------------------------------------
// 5) HMMA GEMM (mma.sync.m16n8k16 — base ISA, assembles on plain sm_103):
//    per CTA: M=128 x N=128 x K=128; 8 warps, warp w owns rows 16w..16w+15.
//    K staged in 32-chunks; sA/sB rows padded to 40 halves (80B stride ->
//    ldmatrix conflict-free). A converted fp32->fp16 while staging.
//    Epilogue: xs = D*dinv[row] -> g_xsh (fp16) ; g_out = 3*dinv*xs (fp32).
// ---------------------------------------------------------------------------
__global__ void __launch_bounds__(256) gemm_kernel(const float* __restrict__ seq) {
    __shared__ __align__(16) __half sA[128 * 40];   // 10240B
    __shared__ __align__(16) __half sB[128 * 40];   // 10240B

    const int tid  = threadIdx.x;
    const int wid  = tid >> 5;
    const int lane = tid & 31;
    const int base = blockIdx.x * 128;
    int rows = NN - base; if (rows > 128) rows = 128;

    float acc[16][4];
    #pragma unroll
    for (int nt = 0; nt < 16; nt++)
        #pragma unroll
        for (int c = 0; c < 4; c++) acc[nt][c] = 0.0f;

    // ldmatrix lane-address components
    const int lr  = lane & 7;          // row within 8-row matrix
    const int sel = lane >> 3;         // which 8x8 matrix (x4)

    for (int k0 = 0; k0 < FT; k0 += 32) {
        __syncthreads();
        // Stage A chunk: row = tid/2, 16 halves at ks = (tid&1)*16
        {
            int r  = tid >> 1;
            int ks = (tid & 1) * 16;
            __half* dst = sA + r * 40 + ks;
            if (r < rows) {
                const float4* src =
                    (const float4*)(seq + (size_t)(base + r) * FT + k0 + ks);
                #pragma unroll
                for (int q = 0; q < 4; q++) {
                    float4 v = src[q];
                    __half2 h0 = __floats2half2_rn(v.x, v.y);
                    __half2 h1 = __floats2half2_rn(v.z, v.w);
                    uint2 pk;
                    pk.x = *(unsigned*)&h0;
                    pk.y = *(unsigned*)&h1;
                    *(uint2*)(dst + q * 4) = pk;
                }
            } else {
                uint2 z = make_uint2(0u, 0u);
                #pragma unroll
                for (int q = 0; q < 4; q++) *(uint2*)(dst + q * 4) = z;
            }
        }
        // Stage B chunk from fp16 W: n = tid/2, 16 halves at ks = (tid&1)*16
        {
            int n  = tid >> 1;
            int ks = (tid & 1) * 16;
            const uint4* src = (const uint4*)(g_Wh + n * FT + k0 + ks);
            *(uint4*)(sB + n * 40 + ks)     = src[0];
            *(uint4*)(sB + n * 40 + ks + 8) = src[1];
        }
        __syncthreads();

        #pragma unroll
        for (int ks = 0; ks < 32; ks += 16) {
            // A fragment (m16 x k16) via ldmatrix.x4
            uint32_t a0, a1, a2, a3;
            {
                int row = wid * 16 + lr + ((sel & 1) ? 8 : 0);
                int kk  = ks + ((sel & 2) ? 8 : 0);
                uint32_t addr = smem_u32(sA + row * 40 + kk);
                asm volatile(
                    "ldmatrix.sync.aligned.m8n8.x4.shared.b16 {%0,%1,%2,%3}, [%4];"
                    : "=r"(a0), "=r"(a1), "=r"(a2), "=r"(a3) : "r"(addr));
            }
            #pragma unroll
            for (int nt = 0; nt < 16; nt++) {
                uint32_t b0, b1;
                int brow = nt * 8 + lr;
                int bk   = ks + ((lane & 8) ? 8 : 0);
                uint32_t baddr = smem_u32(sB + brow * 40 + bk);
                asm volatile(
                    "ldmatrix.sync.aligned.m8n8.x2.shared.b16 {%0,%1}, [%2];"
                    : "=r"(b0), "=r"(b1) : "r"(baddr));
                asm volatile(
                    "mma.sync.aligned.m16n8k16.row.col.f32.f16.f16.f32 "
                    "{%0,%1,%2,%3}, {%4,%5,%6,%7}, {%8,%9}, {%0,%1,%2,%3};"
                    : "+f"(acc[nt][0]), "+f"(acc[nt][1]),
                      "+f"(acc[nt][2]), "+f"(acc[nt][3])
                    : "r"(a0), "r"(a1), "r"(a2), "r"(a3), "r"(b0), "r"(b1));
            }
        }
    }

    // Epilogue: thread holds (row q, cols 2m) and (row q+8, cols 2m) per n-tile
    int q  = lane >> 2;          // 0..7
    int c2 = (lane & 3) * 2;     // col pair base within n-tile
    int r_lo = base + wid * 16 + q;
    int r_hi = r_lo + 8;
    float di_lo = (r_lo < NN) ? g_dinv[r_lo] : 0.0f;
    float di_hi = (r_hi < NN) ? g_dinv[r_hi] : 0.0f;
    float s3_lo = 3.0f * di_lo, s3_hi = 3.0f * di_hi;

    #pragma unroll
    for (int nt = 0; nt < 16; nt++) {
        int col = nt * 8 + c2;
        if (r_lo < NN) {
            float x0 = acc[nt][0] * di_lo, x1 = acc[nt][1] * di_lo;
            __half2 h = __floats2half2_rn(x0, x1);
            *(__half2*)(g_xsh + (size_t)r_lo * FT + col) = h;
            *(float2*)(g_out + (size_t)r_lo * FT + col) =
                make_float2(x0 * s3_lo, x1 * s3_lo);
        }
        if (r_hi < NN) {
            float x2 = acc[nt][2] * di_hi, x3 = acc[nt][3] * di_hi;
            __half2 h = __floats2half2_rn(x2, x3);
            *(__half2*)(g_xsh + (size_t)r_hi * FT + col) = h;
            *(float2*)(g_out + (size_t)r_hi * FT + col) =
                make_float2(x2 * s3_hi, x3 * s3_hi);
        }
    }
}

// ---------------------------------------------------------------------------
// 6) Edge aggregation: g_out[row] += (w[e]*dinv[row]) * xs_fp16[col]
//    One warp per edge; 8B fp16 gather, one red.global.add.v4.f32.
// ---------------------------------------------------------------------------
__global__ void __launch_bounds__(256) agg_kernel(const int* __restrict__ ei,
                                                  const float* __restrict__ w) {
    int gw   = (blockIdx.x * blockDim.x + threadIdx.x) >> 5;   // edge id
    int lane = threadIdx.x & 31;
    if (gw >= EE) return;

    int r = ei[gw];        // row
    int c = ei[EE + gw];   // col
    float s = w[gw] * g_dinv[r];

    uint2 pk = *(const uint2*)(g_xsh + (size_t)c * FT + lane * 4);
    __half2 h01 = *(__half2*)&pk.x;
    __half2 h23 = *(__half2*)&pk.y;
    float2 f01 = __half22float2(h01);
    float2 f23 = __half22float2(h23);

    float* p = g_out + (size_t)r * FT + lane * 4;
    asm volatile("red.global.add.v4.f32 [%0], {%1, %2, %3, %4};"
                 :: "l"(p),
                    "f"(f01.x * s), "f"(f01.y * s),
                    "f"(f23.x * s), "f"(f23.y * s)
                 : "memory");
}

// ---------------------------------------------------------------------------
// 7) ReLU + copy to d_out (plain vector stores only on harness memory)
// ---------------------------------------------------------------------------
__global__ void relu_copy_kernel(float* __restrict__ out) {
    int i = blockIdx.x * blockDim.x + threadIdx.x;   // float4 index
    if (i >= NN * (FT / 4)) return;
    float4 v = ((const float4*)g_out)[i];
    v.x = fmaxf(v.x, 0.0f); v.y = fmaxf(v.y, 0.0f);
    v.z = fmaxf(v.z, 0.0f); v.w = fmaxf(v.w, 0.0f);
    ((float4*)out)[i] = v;
}

// ---------------------------------------------------------------------------
extern "C" void kernel_launch(void* const* d_in, const int* in_sizes, int n_in,
                              void* d_out, int out_size) {
    // Resolve inputs by element count (robust to metadata ordering):
    //   seq: NN*FT (12.8M f32), edge_weight: EE (1.6M f32),
    //   W: FT*FT (16384 f32), edge_index: 2*EE (3.2M i32)
    const float* seq = nullptr;
    const float* ew  = nullptr;
    const float* W   = nullptr;
    const int*   ei  = nullptr;
    for (int i = 0; i < n_in; i++) {
        if      (in_sizes[i] == NN * FT) seq = (const float*)d_in[i];
        else if (in_sizes[i] == EE)      ew  = (const float*)d_in[i];
        else if (in_sizes[i] == FT * FT) W   = (const float*)d_in[i];
        else if (in_sizes[i] == 2 * EE)  ei  = (const int*)d_in[i];
    }
    float* out = (float*)d_out;

    wh_kernel<<<(FT * FT + 255) / 256, 256>>>(W);
    init_deg_kernel<<<(NN + 255) / 256, 256>>>();
    deg_kernel<<<(EE + 255) / 256, 256>>>(ei, ew);
    dinv_kernel<<<(NN + 255) / 256, 256>>>();
    gemm_kernel<<<(NN + 127) / 128, 256>>>(seq);      // HMMA; epilogue needs dinv
    agg_kernel<<<(EE * 32) / 256, 256>>>(ei, ew);     // 1 warp / edge, exact grid
    relu_copy_kernel<<<(NN * (FT / 4) + 255) / 256, 256>>>(out);
}

// round 16
// speedup vs baseline: 2.1719x; 1.6240x over previous
#include <cuda_runtime.h>
#include <cuda_fp16.h>
#include <cstdint>

#define NN 100000
#define EE 1600000
#define FT 128
#define NBLK 391   // ceil(NN/256)

// ---------------------------------------------------------------------------
// Scratch (allocation-free rule: __device__ globals)
// ---------------------------------------------------------------------------
__device__ __align__(16) __half g_xsh[(size_t)NN * FT];   // fp16 (seq@W^T)*dinv[row]
__device__ __align__(16) float  g_deg[NN];
__device__ __align__(16) float  g_dinv[NN];
__device__ __align__(16) __half g_Wh[FT * FT];            // W in fp16, row-major [o][k]
__device__ __align__(16) float  g_eval[EE];               // w[e]*dinv[row], CSR order
__device__ int g_ecol[EE];                                // col, CSR order
__device__ int g_rowptr[NN + 1];
__device__ int g_cnt[NN];                                 // histogram, then cursor
__device__ int g_bsum[512];                               // per-block count sums

__device__ __forceinline__ uint32_t smem_u32(const void* p) {
    uint32_t a;
    asm("{ .reg .u64 t; cvta.to.shared.u64 t, %1; cvt.u32.u64 %0, t; }"
        : "=r"(a) : "l"(p));
    return a;
}

// ---------------------------------------------------------------------------
// 1) W -> fp16 (one-time, tiny)
// ---------------------------------------------------------------------------
__global__ void wh_kernel(const float* __restrict__ W) {
    int idx = blockIdx.x * blockDim.x + threadIdx.x;
    if (idx < FT * FT) g_Wh[idx] = __float2half_rn(W[idx]);
}

// ---------------------------------------------------------------------------
// 2) deg init to self-loop fill (3.0), counters to 0
// ---------------------------------------------------------------------------
__global__ void init_kernel() {
    int i = blockIdx.x * blockDim.x + threadIdx.x;
    if (i < NN) { g_deg[i] = 3.0f; g_cnt[i] = 0; }
}

// ---------------------------------------------------------------------------
// 3) Degree accumulation + row histogram (edge_index is int32)
// ---------------------------------------------------------------------------
__global__ void deg_hist_kernel(const int* __restrict__ ei,
                                const float* __restrict__ w) {
    int e = blockIdx.x * blockDim.x + threadIdx.x;
    if (e < EE) {
        int r = ei[e];
        atomicAdd(&g_deg[r], w[e]);
        atomicAdd(&g_cnt[r], 1);
    }
}

// ---------------------------------------------------------------------------
// 4) dinv = rsqrt(deg)  (deg >= 3 always, guard vacuous)
// ---------------------------------------------------------------------------
__global__ void dinv_kernel() {
    int i = blockIdx.x * blockDim.x + threadIdx.x;
    if (i < NN) g_dinv[i] = rsqrtf(g_deg[i]);
}

// ---------------------------------------------------------------------------
// 5a) Scan level 1: per-block (256) reduction of g_cnt -> g_bsum[block]
// ---------------------------------------------------------------------------
__global__ void __launch_bounds__(256) scan1_kernel() {
    __shared__ int sh[256];
    int t = threadIdx.x;
    int i = blockIdx.x * 256 + t;
    sh[t] = (i < NN) ? g_cnt[i] : 0;
    __syncthreads();
    #pragma unroll
    for (int off = 128; off > 0; off >>= 1) {
        if (t < off) sh[t] += sh[t + off];
        __syncthreads();
    }
    if (t == 0) g_bsum[blockIdx.x] = sh[0];
}

// ---------------------------------------------------------------------------
// 5b) Scan level 2: exclusive scan of 391 block sums (one 512-thread block)
// ---------------------------------------------------------------------------
__global__ void __launch_bounds__(512) scan2_kernel() {
    __shared__ int sh[512];
    int t = threadIdx.x;
    int v = (t < NBLK) ? g_bsum[t] : 0;
    sh[t] = v;
    __syncthreads();
    #pragma unroll
    for (int off = 1; off < 512; off <<= 1) {
        int x = (t >= off) ? sh[t - off] : 0;
        __syncthreads();
        sh[t] += x;
        __syncthreads();
    }
    if (t < NBLK) g_bsum[t] = sh[t] - v;   // exclusive
    if (t == 0) g_rowptr[NN] = EE;         // total is a known constant
}

// ---------------------------------------------------------------------------
// 5c) Scan level 3: per-block exclusive scan + block offset -> g_rowptr;
//     reset g_cnt for the scatter cursors.
// ---------------------------------------------------------------------------
__global__ void __launch_bounds__(256) scan3_kernel() {
    __shared__ int sh[256];
    int t = threadIdx.x;
    int i = blockIdx.x * 256 + t;
    int v = (i < NN) ? g_cnt[i] : 0;
    sh[t] = v;
    __syncthreads();
    #pragma unroll
    for (int off = 1; off < 256; off <<= 1) {
        int x = (t >= off) ? sh[t - off] : 0;
        __syncthreads();
        sh[t] += x;
        __syncthreads();
    }
    if (i < NN) {
        g_rowptr[i] = g_bsum[blockIdx.x] + sh[t] - v;   // exclusive
        g_cnt[i] = 0;
    }
}

// ---------------------------------------------------------------------------
// 6) Scatter edges into CSR; fold w[e]*dinv[row] into the stored value
// ---------------------------------------------------------------------------
__global__ void scatter_kernel(const int* __restrict__ ei,
                               const float* __restrict__ w) {
    int e = blockIdx.x * blockDim.x + threadIdx.x;
    if (e >= EE) return;
    int r = ei[e];
    int c = ei[EE + e];
    int pos = g_rowptr[r] + atomicAdd(&g_cnt[r], 1);
    g_ecol[pos] = c;
    g_eval[pos] = w[e] * g_dinv[r];
}

// ---------------------------------------------------------------------------
// 7) HMMA GEMM (mma.sync.m16n8k16, base ISA): g_xsh[n] = fp16((seq@W^T)*dinv)
//    per CTA: M=128 x N=128 x K=128; 8 warps; sA/sB rows padded to 40 halves.
// ---------------------------------------------------------------------------
__global__ void __launch_bounds__(256) gemm_kernel(const float* __restrict__ seq) {
    __shared__ __align__(16) __half sA[128 * 40];   // 10240B
    __shared__ __align__(16) __half sB[128 * 40];   // 10240B

    const int tid  = threadIdx.x;
    const int wid  = tid >> 5;
    const int lane = tid & 31;
    const int base = blockIdx.x * 128;
    int rows = NN - base; if (rows > 128) rows = 128;

    float acc[16][4];
    #pragma unroll
    for (int nt = 0; nt < 16; nt++)
        #pragma unroll
        for (int c = 0; c < 4; c++) acc[nt][c] = 0.0f;

    const int lr  = lane & 7;
    const int sel = lane >> 3;

    for (int k0 = 0; k0 < FT; k0 += 32) {
        __syncthreads();
        // Stage A chunk: row = tid/2, 16 halves at ks = (tid&1)*16
        {
            int r  = tid >> 1;
            int ks = (tid & 1) * 16;
            __half* dst = sA + r * 40 + ks;
            if (r < rows) {
                const float4* src =
                    (const float4*)(seq + (size_t)(base + r) * FT + k0 + ks);
                #pragma unroll
                for (int q = 0; q < 4; q++) {
                    float4 v = src[q];
                    __half2 h0 = __floats2half2_rn(v.x, v.y);
                    __half2 h1 = __floats2half2_rn(v.z, v.w);
                    uint2 pk;
                    pk.x = *(unsigned*)&h0;
                    pk.y = *(unsigned*)&h1;
                    *(uint2*)(dst + q * 4) = pk;
                }
            } else {
                uint2 z = make_uint2(0u, 0u);
                #pragma unroll
                for (int q = 0; q < 4; q++) *(uint2*)(dst + q * 4) = z;
            }
        }
        // Stage B chunk from fp16 W
        {
            int n  = tid >> 1;
            int ks = (tid & 1) * 16;
            const uint4* src = (const uint4*)(g_Wh + n * FT + k0 + ks);
            *(uint4*)(sB + n * 40 + ks)     = src[0];
            *(uint4*)(sB + n * 40 + ks + 8) = src[1];
        }
        __syncthreads();

        #pragma unroll
        for (int ks = 0; ks < 32; ks += 16) {
            uint32_t a0, a1, a2, a3;
            {
                int row = wid * 16 + lr + ((sel & 1) ? 8 : 0);
                int kk  = ks + ((sel & 2) ? 8 : 0);
                uint32_t addr = smem_u32(sA + row * 40 + kk);
                asm volatile(
                    "ldmatrix.sync.aligned.m8n8.x4.shared.b16 {%0,%1,%2,%3}, [%4];"
                    : "=r"(a0), "=r"(a1), "=r"(a2), "=r"(a3) : "r"(addr));
            }
            #pragma unroll
            for (int nt = 0; nt < 16; nt++) {
                uint32_t b0, b1;
                int brow = nt * 8 + lr;
                int bk   = ks + ((lane & 8) ? 8 : 0);
                uint32_t baddr = smem_u32(sB + brow * 40 + bk);
                asm volatile(
                    "ldmatrix.sync.aligned.m8n8.x2.shared.b16 {%0,%1}, [%2];"
                    : "=r"(b0), "=r"(b1) : "r"(baddr));
                asm volatile(
                    "mma.sync.aligned.m16n8k16.row.col.f32.f16.f16.f32 "
                    "{%0,%1,%2,%3}, {%4,%5,%6,%7}, {%8,%9}, {%0,%1,%2,%3};"
                    : "+f"(acc[nt][0]), "+f"(acc[nt][1]),
                      "+f"(acc[nt][2]), "+f"(acc[nt][3])
                    : "r"(a0), "r"(a1), "r"(a2), "r"(a3), "r"(b0), "r"(b1));
            }
        }
    }

    // Epilogue: xs*dinv -> g_xsh (fp16 only; self-loop handled in agg)
    int q  = lane >> 2;
    int c2 = (lane & 3) * 2;
    int r_lo = base + wid * 16 + q;
    int r_hi = r_lo + 8;
    float di_lo = (r_lo < NN) ? g_dinv[r_lo] : 0.0f;
    float di_hi = (r_hi < NN) ? g_dinv[r_hi] : 0.0f;

    #pragma unroll
    for (int nt = 0; nt < 16; nt++) {
        int col = nt * 8 + c2;
        if (r_lo < NN) {
            __half2 h = __floats2half2_rn(acc[nt][0] * di_lo, acc[nt][1] * di_lo);
            *(__half2*)(g_xsh + (size_t)r_lo * FT + col) = h;
        }
        if (r_hi < NN) {
            __half2 h = __floats2half2_rn(acc[nt][2] * di_hi, acc[nt][3] * di_hi);
            *(__half2*)(g_xsh + (size_t)r_hi * FT + col) = h;
        }
    }
}

// ---------------------------------------------------------------------------
// 8) CSR aggregation: warp per row, register accumulation, NO atomics.
//    out[n] = relu( 3*dinv[n]*xs[n] + sum_e val[e] * xs[col[e]] )
//    written directly to d_out (plain vector stores).
// ---------------------------------------------------------------------------
__global__ void __launch_bounds__(256) agg_kernel(float* __restrict__ out) {
    int n    = (blockIdx.x * blockDim.x + threadIdx.x) >> 5;
    int lane = threadIdx.x & 31;
    if (n >= NN) return;

    int start = g_rowptr[n];
    int end   = g_rowptr[n + 1];

    // self-loop: 3*dinv[n] * xs[n]
    float s3 = 3.0f * g_dinv[n];
    uint2 pk = *(const uint2*)(g_xsh + (size_t)n * FT + lane * 4);
    float2 f01 = __half22float2(*(__half2*)&pk.x);
    float2 f23 = __half22float2(*(__half2*)&pk.y);
    float4 acc = make_float4(f01.x * s3, f01.y * s3, f23.x * s3, f23.y * s3);

    int idx = start;
    for (; idx + 2 <= end; idx += 2) {     // 2-way unroll for MLP
        int   c0 = g_ecol[idx],  c1 = g_ecol[idx + 1];
        float s0 = g_eval[idx],  s1 = g_eval[idx + 1];
        uint2 p0 = *(const uint2*)(g_xsh + (size_t)c0 * FT + lane * 4);
        uint2 p1 = *(const uint2*)(g_xsh + (size_t)c1 * FT + lane * 4);
        float2 a01 = __half22float2(*(__half2*)&p0.x);
        float2 a23 = __half22float2(*(__half2*)&p0.y);
        float2 b01 = __half22float2(*(__half2*)&p1.x);
        float2 b23 = __half22float2(*(__half2*)&p1.y);
        acc.x += s0 * a01.x + s1 * b01.x;
        acc.y += s0 * a01.y + s1 * b01.y;
        acc.z += s0 * a23.x + s1 * b23.x;
        acc.w += s0 * a23.y + s1 * b23.y;
    }
    if (idx < end) {
        int   c = g_ecol[idx];
        float s = g_eval[idx];
        uint2 p = *(const uint2*)(g_xsh + (size_t)c * FT + lane * 4);
        float2 a01 = __half22float2(*(__half2*)&p.x);
        float2 a23 = __half22float2(*(__half2*)&p.y);
        acc.x += s * a01.x; acc.y += s * a01.y;
        acc.z += s * a23.x; acc.w += s * a23.y;
    }

    acc.x = fmaxf(acc.x, 0.0f); acc.y = fmaxf(acc.y, 0.0f);
    acc.z = fmaxf(acc.z, 0.0f); acc.w = fmaxf(acc.w, 0.0f);
    *(float4*)(out + (size_t)n * FT + lane * 4) = acc;
}

// ---------------------------------------------------------------------------
extern "C" void kernel_launch(void* const* d_in, const int* in_sizes, int n_in,
                              void* d_out, int out_size) {
    // Resolve inputs by element count (robust to metadata ordering):
    //   seq: NN*FT (12.8M f32), edge_weight: EE (1.6M f32),
    //   W: FT*FT (16384 f32), edge_index: 2*EE (3.2M i32)
    const float* seq = nullptr;
    const float* ew  = nullptr;
    const float* W   = nullptr;
    const int*   ei  = nullptr;
    for (int i = 0; i < n_in; i++) {
        if      (in_sizes[i] == NN * FT) seq = (const float*)d_in[i];
        else if (in_sizes[i] == EE)      ew  = (const float*)d_in[i];
        else if (in_sizes[i] == FT * FT) W   = (const float*)d_in[i];
        else if (in_sizes[i] == 2 * EE)  ei  = (const int*)d_in[i];
    }
    float* out = (float*)d_out;

    wh_kernel<<<(FT * FT + 255) / 256, 256>>>(W);
    init_kernel<<<NBLK, 256>>>();
    deg_hist_kernel<<<(EE + 255) / 256, 256>>>(ei, ew);
    dinv_kernel<<<NBLK, 256>>>();
    scan1_kernel<<<NBLK, 256>>>();
    scan2_kernel<<<1, 512>>>();
    scan3_kernel<<<NBLK, 256>>>();
    scatter_kernel<<<(EE + 255) / 256, 256>>>(ei, ew);
    gemm_kernel<<<(NN + 127) / 128, 256>>>(seq);          // HMMA; needs dinv
    agg_kernel<<<(NN * 32 + 255) / 256, 256>>>(out);      // warp per row -> d_out
}

// round 17
// speedup vs baseline: 2.5772x; 1.1866x over previous
#include <cuda_runtime.h>
#include <cuda_fp16.h>
#include <cstdint>

#define NN 100000
#define EE 1600000
#define FT 128
#define NBLK 391   // ceil(NN/256)

// ---------------------------------------------------------------------------
// Scratch (allocation-free rule: __device__ globals)
// ---------------------------------------------------------------------------
__device__ __align__(16) __half g_xsh[(size_t)NN * FT];   // fp16 (seq@W^T)*dinv[row]
__device__ __align__(16) float  g_deg[NN];
__device__ __align__(16) float  g_dinv[NN];
__device__ __align__(16) __half g_Wh[FT * FT];            // W in fp16, row-major [o][k]
__device__ __align__(16) float  g_eval[EE];               // w[e]*dinv[row], CSR order
__device__ int g_ecol[EE];                                // col, CSR order
__device__ int g_rowptr[NN + 1];
__device__ int g_cnt[NN];                                 // histogram, then cursor
__device__ int g_bsum[512];                               // per-block count sums

__device__ __forceinline__ uint32_t smem_u32(const void* p) {
    uint32_t a;
    asm("{ .reg .u64 t; cvta.to.shared.u64 t, %1; cvt.u32.u64 %0, t; }"
        : "=r"(a) : "l"(p));
    return a;
}

// ---------------------------------------------------------------------------
// 1) Fused prep: W -> fp16 AND deg/cnt init (disjoint index ranges)
// ---------------------------------------------------------------------------
__global__ void prep_kernel(const float* __restrict__ W) {
    int idx = blockIdx.x * blockDim.x + threadIdx.x;
    if (idx < FT * FT) g_Wh[idx] = __float2half_rn(W[idx]);
    if (idx < NN) { g_deg[idx] = 3.0f; g_cnt[idx] = 0; }
}

// ---------------------------------------------------------------------------
// 2) Degree accumulation + row histogram (edge_index is int32)
// ---------------------------------------------------------------------------
__global__ void deg_hist_kernel(const int* __restrict__ ei,
                                const float* __restrict__ w) {
    int e = blockIdx.x * blockDim.x + threadIdx.x;
    if (e < EE) {
        int r = ei[e];
        atomicAdd(&g_deg[r], w[e]);
        atomicAdd(&g_cnt[r], 1);
    }
}

// ---------------------------------------------------------------------------
// 3a) Scan level 1 + fused dinv = rsqrt(deg)
// ---------------------------------------------------------------------------
__global__ void __launch_bounds__(256) scan1_kernel() {
    __shared__ int sh[256];
    int t = threadIdx.x;
    int i = blockIdx.x * 256 + t;
    int v = 0;
    if (i < NN) {
        v = g_cnt[i];
        g_dinv[i] = rsqrtf(g_deg[i]);   // deg >= 3 always
    }
    sh[t] = v;
    __syncthreads();
    #pragma unroll
    for (int off = 128; off > 0; off >>= 1) {
        if (t < off) sh[t] += sh[t + off];
        __syncthreads();
    }
    if (t == 0) g_bsum[blockIdx.x] = sh[0];
}

// ---------------------------------------------------------------------------
// 3b) Scan level 2: exclusive scan of 391 block sums (one 512-thread block)
// ---------------------------------------------------------------------------
__global__ void __launch_bounds__(512) scan2_kernel() {
    __shared__ int sh[512];
    int t = threadIdx.x;
    int v = (t < NBLK) ? g_bsum[t] : 0;
    sh[t] = v;
    __syncthreads();
    #pragma unroll
    for (int off = 1; off < 512; off <<= 1) {
        int x = (t >= off) ? sh[t - off] : 0;
        __syncthreads();
        sh[t] += x;
        __syncthreads();
    }
    if (t < NBLK) g_bsum[t] = sh[t] - v;   // exclusive
    if (t == 0) g_rowptr[NN] = EE;         // total is a known constant
}

// ---------------------------------------------------------------------------
// 3c) Scan level 3: per-block exclusive scan + block offset -> g_rowptr;
//     reset g_cnt for the scatter cursors.
// ---------------------------------------------------------------------------
__global__ void __launch_bounds__(256) scan3_kernel() {
    __shared__ int sh[256];
    int t = threadIdx.x;
    int i = blockIdx.x * 256 + t;
    int v = (i < NN) ? g_cnt[i] : 0;
    sh[t] = v;
    __syncthreads();
    #pragma unroll
    for (int off = 1; off < 256; off <<= 1) {
        int x = (t >= off) ? sh[t - off] : 0;
        __syncthreads();
        sh[t] += x;
        __syncthreads();
    }
    if (i < NN) {
        g_rowptr[i] = g_bsum[blockIdx.x] + sh[t] - v;   // exclusive
        g_cnt[i] = 0;
    }
}

// ---------------------------------------------------------------------------
// 4) Scatter edges into CSR; fold w[e]*dinv[row] into the stored value
// ---------------------------------------------------------------------------
__global__ void scatter_kernel(const int* __restrict__ ei,
                               const float* __restrict__ w) {
    int e = blockIdx.x * blockDim.x + threadIdx.x;
    if (e >= EE) return;
    int r = ei[e];
    int c = ei[EE + e];
    int pos = g_rowptr[r] + atomicAdd(&g_cnt[r], 1);
    g_ecol[pos] = c;
    g_eval[pos] = w[e] * g_dinv[r];
}

// ---------------------------------------------------------------------------
// 5) HMMA GEMM (mma.sync.m16n8k16, base ISA): g_xsh[n] = fp16((seq@W^T)*dinv)
//    per CTA: M=128 x N=128 x K=128; 8 warps; sA/sB rows padded to 40 halves.
//    B fragments loaded pairwise with ldmatrix.x4 (2 n-tiles per LDSM).
// ---------------------------------------------------------------------------
__global__ void __launch_bounds__(256) gemm_kernel(const float* __restrict__ seq) {
    __shared__ __align__(16) __half sA[128 * 40];   // 10240B
    __shared__ __align__(16) __half sB[128 * 40];   // 10240B

    const int tid  = threadIdx.x;
    const int wid  = tid >> 5;
    const int lane = tid & 31;
    const int base = blockIdx.x * 128;
    int rows = NN - base; if (rows > 128) rows = 128;

    float acc[16][4];
    #pragma unroll
    for (int nt = 0; nt < 16; nt++)
        #pragma unroll
        for (int c = 0; c < 4; c++) acc[nt][c] = 0.0f;

    const int lr  = lane & 7;
    const int sel = lane >> 3;

    for (int k0 = 0; k0 < FT; k0 += 32) {
        __syncthreads();
        // Stage A chunk: row = tid/2, 16 halves at ks = (tid&1)*16
        {
            int r  = tid >> 1;
            int ks = (tid & 1) * 16;
            __half* dst = sA + r * 40 + ks;
            if (r < rows) {
                const float4* src =
                    (const float4*)(seq + (size_t)(base + r) * FT + k0 + ks);
                #pragma unroll
                for (int q = 0; q < 4; q++) {
                    float4 v = src[q];
                    __half2 h0 = __floats2half2_rn(v.x, v.y);
                    __half2 h1 = __floats2half2_rn(v.z, v.w);
                    uint2 pk;
                    pk.x = *(unsigned*)&h0;
                    pk.y = *(unsigned*)&h1;
                    *(uint2*)(dst + q * 4) = pk;
                }
            } else {
                uint2 z = make_uint2(0u, 0u);
                #pragma unroll
                for (int q = 0; q < 4; q++) *(uint2*)(dst + q * 4) = z;
            }
        }
        // Stage B chunk from fp16 W
        {
            int n  = tid >> 1;
            int ks = (tid & 1) * 16;
            const uint4* src = (const uint4*)(g_Wh + n * FT + k0 + ks);
            *(uint4*)(sB + n * 40 + ks)     = src[0];
            *(uint4*)(sB + n * 40 + ks + 8) = src[1];
        }
        __syncthreads();

        #pragma unroll
        for (int ks = 0; ks < 32; ks += 16) {
            // A fragment (m16 x k16) via ldmatrix.x4
            uint32_t a0, a1, a2, a3;
            {
                int row = wid * 16 + lr + ((sel & 1) ? 8 : 0);
                int kk  = ks + ((sel & 2) ? 8 : 0);
                uint32_t addr = smem_u32(sA + row * 40 + kk);
                asm volatile(
                    "ldmatrix.sync.aligned.m8n8.x4.shared.b16 {%0,%1,%2,%3}, [%4];"
                    : "=r"(a0), "=r"(a1), "=r"(a2), "=r"(a3) : "r"(addr));
            }
            // B fragments: 2 n-tiles per ldmatrix.x4
            //   lanes 0-7:   (nt=2p,   k+0)   -> b0
            //   lanes 8-15:  (nt=2p,   k+8)   -> b1
            //   lanes 16-23: (nt=2p+1, k+0)   -> b2
            //   lanes 24-31: (nt=2p+1, k+8)   -> b3
            #pragma unroll
            for (int p = 0; p < 8; p++) {
                uint32_t b0, b1, b2, b3;
                int nt   = p * 2 + ((lane >> 4) & 1);
                int bk   = ks + (lane & 8);
                uint32_t baddr = smem_u32(sB + (nt * 8 + lr) * 40 + bk);
                asm volatile(
                    "ldmatrix.sync.aligned.m8n8.x4.shared.b16 {%0,%1,%2,%3}, [%4];"
                    : "=r"(b0), "=r"(b1), "=r"(b2), "=r"(b3) : "r"(baddr));
                asm volatile(
                    "mma.sync.aligned.m16n8k16.row.col.f32.f16.f16.f32 "
                    "{%0,%1,%2,%3}, {%4,%5,%6,%7}, {%8,%9}, {%0,%1,%2,%3};"
                    : "+f"(acc[p * 2][0]), "+f"(acc[p * 2][1]),
                      "+f"(acc[p * 2][2]), "+f"(acc[p * 2][3])
                    : "r"(a0), "r"(a1), "r"(a2), "r"(a3), "r"(b0), "r"(b1));
                asm volatile(
                    "mma.sync.aligned.m16n8k16.row.col.f32.f16.f16.f32 "
                    "{%0,%1,%2,%3}, {%4,%5,%6,%7}, {%8,%9}, {%0,%1,%2,%3};"
                    : "+f"(acc[p * 2 + 1][0]), "+f"(acc[p * 2 + 1][1]),
                      "+f"(acc[p * 2 + 1][2]), "+f"(acc[p * 2 + 1][3])
                    : "r"(a0), "r"(a1), "r"(a2), "r"(a3), "r"(b2), "r"(b3));
            }
        }
    }

    // Epilogue: xs*dinv -> g_xsh (fp16 only; self-loop handled in agg)
    int q  = lane >> 2;
    int c2 = (lane & 3) * 2;
    int r_lo = base + wid * 16 + q;
    int r_hi = r_lo + 8;
    float di_lo = (r_lo < NN) ? g_dinv[r_lo] : 0.0f;
    float di_hi = (r_hi < NN) ? g_dinv[r_hi] : 0.0f;

    #pragma unroll
    for (int nt = 0; nt < 16; nt++) {
        int col = nt * 8 + c2;
        if (r_lo < NN) {
            __half2 h = __floats2half2_rn(acc[nt][0] * di_lo, acc[nt][1] * di_lo);
            *(__half2*)(g_xsh + (size_t)r_lo * FT + col) = h;
        }
        if (r_hi < NN) {
            __half2 h = __floats2half2_rn(acc[nt][2] * di_hi, acc[nt][3] * di_hi);
            *(__half2*)(g_xsh + (size_t)r_hi * FT + col) = h;
        }
    }
}

// ---------------------------------------------------------------------------
// 6) CSR aggregation: warp per row, register accumulation, NO atomics.
//    out[n] = relu( 3*dinv[n]*xs[n] + sum_e val[e] * xs[col[e]] )
//    4-way unrolled gather for MLP; written directly to d_out.
// ---------------------------------------------------------------------------
__global__ void __launch_bounds__(256) agg_kernel(float* __restrict__ out) {
    int n    = (blockIdx.x * blockDim.x + threadIdx.x) >> 5;
    int lane = threadIdx.x & 31;
    if (n >= NN) return;

    int start = g_rowptr[n];
    int end   = g_rowptr[n + 1];

    // self-loop: 3*dinv[n] * xs[n]
    float s3 = 3.0f * g_dinv[n];
    uint2 pk = *(const uint2*)(g_xsh + (size_t)n * FT + lane * 4);
    float2 f01 = __half22float2(*(__half2*)&pk.x);
    float2 f23 = __half22float2(*(__half2*)&pk.y);
    float4 acc = make_float4(f01.x * s3, f01.y * s3, f23.x * s3, f23.y * s3);

    int idx = start;
    for (; idx + 4 <= end; idx += 4) {     // 4-way unroll for MLP
        int   c0 = g_ecol[idx],     c1 = g_ecol[idx + 1];
        int   c2 = g_ecol[idx + 2], c3 = g_ecol[idx + 3];
        float s0 = g_eval[idx],     s1 = g_eval[idx + 1];
        float s2 = g_eval[idx + 2], s3e = g_eval[idx + 3];
        uint2 p0 = *(const uint2*)(g_xsh + (size_t)c0 * FT + lane * 4);
        uint2 p1 = *(const uint2*)(g_xsh + (size_t)c1 * FT + lane * 4);
        uint2 p2 = *(const uint2*)(g_xsh + (size_t)c2 * FT + lane * 4);
        uint2 p3 = *(const uint2*)(g_xsh + (size_t)c3 * FT + lane * 4);
        float2 a01 = __half22float2(*(__half2*)&p0.x);
        float2 a23 = __half22float2(*(__half2*)&p0.y);
        float2 b01 = __half22float2(*(__half2*)&p1.x);
        float2 b23 = __half22float2(*(__half2*)&p1.y);
        float2 d01 = __half22float2(*(__half2*)&p2.x);
        float2 d23 = __half22float2(*(__half2*)&p2.y);
        float2 e01 = __half22float2(*(__half2*)&p3.x);
        float2 e23 = __half22float2(*(__half2*)&p3.y);
        acc.x += s0 * a01.x + s1 * b01.x + s2 * d01.x + s3e * e01.x;
        acc.y += s0 * a01.y + s1 * b01.y + s2 * d01.y + s3e * e01.y;
        acc.z += s0 * a23.x + s1 * b23.x + s2 * d23.x + s3e * e23.x;
        acc.w += s0 * a23.y + s1 * b23.y + s2 * d23.y + s3e * e23.y;
    }
    for (; idx < end; idx++) {
        int   c = g_ecol[idx];
        float s = g_eval[idx];
        uint2 p = *(const uint2*)(g_xsh + (size_t)c * FT + lane * 4);
        float2 a01 = __half22float2(*(__half2*)&p.x);
        float2 a23 = __half22float2(*(__half2*)&p.y);
        acc.x += s * a01.x; acc.y += s * a01.y;
        acc.z += s * a23.x; acc.w += s * a23.y;
    }

    acc.x = fmaxf(acc.x, 0.0f); acc.y = fmaxf(acc.y, 0.0f);
    acc.z = fmaxf(acc.z, 0.0f); acc.w = fmaxf(acc.w, 0.0f);
    *(float4*)(out + (size_t)n * FT + lane * 4) = acc;
}

// ---------------------------------------------------------------------------
extern "C" void kernel_launch(void* const* d_in, const int* in_sizes, int n_in,
                              void* d_out, int out_size) {
    // Resolve inputs by element count (robust to metadata ordering):
    //   seq: NN*FT (12.8M f32), edge_weight: EE (1.6M f32),
    //   W: FT*FT (16384 f32), edge_index: 2*EE (3.2M i32)
    const float* seq = nullptr;
    const float* ew  = nullptr;
    const float* W   = nullptr;
    const int*   ei  = nullptr;
    for (int i = 0; i < n_in; i++) {
        if      (in_sizes[i] == NN * FT) seq = (const float*)d_in[i];
        else if (in_sizes[i] == EE)      ew  = (const float*)d_in[i];
        else if (in_sizes[i] == FT * FT) W   = (const float*)d_in[i];
        else if (in_sizes[i] == 2 * EE)  ei  = (const int*)d_in[i];
    }
    float* out = (float*)d_out;

    prep_kernel<<<NBLK, 256>>>(W);                        // W->fp16 + deg/cnt init
    deg_hist_kernel<<<(EE + 255) / 256, 256>>>(ei, ew);
    scan1_kernel<<<NBLK, 256>>>();                        // + fused dinv
    scan2_kernel<<<1, 512>>>();
    scan3_kernel<<<NBLK, 256>>>();
    scatter_kernel<<<(EE + 255) / 256, 256>>>(ei, ew);
    gemm_kernel<<<(NN + 127) / 128, 256>>>(seq);          // HMMA; needs dinv
    agg_kernel<<<(NN * 32 + 255) / 256, 256>>>(out);      // warp per row -> d_out
}